// round 1
// baseline (speedup 1.0000x reference)
#include <cuda_runtime.h>
#include <math.h>

#define NB 4096
#define NP 32
#define NC 512
#define PFW (NC + 4)   // padded pivot row (floats) to break smem bank conflicts
#define TW  68         // padded k-major tile width for ii GEMM (16B-aligned rows)
#define NT  64         // 4096/64 tile grid
#define NBLK_II (NT * (NT + 1) / 2)   // 2080 upper-triangle tiles

__device__ double g_acc[3];        // [0]=ii sum, [1]=tt sum, [2]=it sum
__device__ float  g_fn[NB * NC];   // L2-normalized feats

__device__ __forceinline__ float warp_sum(float v) {
#pragma unroll
    for (int o = 16; o > 0; o >>= 1) v += __shfl_xor_sync(0xffffffffu, v, o);
    return v;
}

__global__ void k_init() {
    if (threadIdx.x < 3) g_acc[threadIdx.x] = 0.0;
}

// One block per feats row: compute L2 norm, write normalized row to g_fn.
__global__ void k_norm_feats(const float* __restrict__ feats) {
    __shared__ float red[4];
    int b = blockIdx.x, t = threadIdx.x;  // 128 threads, 128 float4 per row
    const float4* src = (const float4*)(feats + (size_t)b * NC);
    float4 v = src[t];
    float s = v.x * v.x + v.y * v.y + v.z * v.z + v.w * v.w;
    s = warp_sum(s);
    if ((t & 31) == 0) red[t >> 5] = s;
    __syncthreads();
    float tot = red[0] + red[1] + red[2] + red[3];
    float inv = 1.0f / fmaxf(sqrtf(tot), 1e-12f);
    v.x *= inv; v.y *= inv; v.z *= inv; v.w *= inv;
    ((float4*)(g_fn + (size_t)b * NC))[t] = v;
}

// One block per batch index b: normalize pivot rows into smem, compute
// text-text gram (32x32 over C=512) with 2x2 register tiling, and the
// image-text row dots. Fused so pivot_features (256 MB) is read exactly once.
__global__ void k_pivot(const float* __restrict__ pf,
                        const float* __restrict__ ps,
                        const float* __restrict__ targets) {
    extern __shared__ float sm[];
    float* pf_s = sm;                    // NP * PFW
    float* fn_s = pf_s + NP * PFW;       // NC
    float* ps_s = fn_s + NC;             // NP
    float* red  = ps_s + NP;             // 16

    int b = blockIdx.x, tid = threadIdx.x;   // 256 threads
    int lane = tid & 31, w = tid >> 5;       // 8 warps

    // load normalized feats row b into smem
    {
        const float4* src = (const float4*)(g_fn + (size_t)b * NC);
        float4* dst = (float4*)fn_s;
        for (int i = tid; i < NC / 4; i += 256) dst[i] = src[i];
    }
    if (tid < NP) ps_s[tid] = ps[b * NP + tid];

    // normalize pivot rows: warp w handles rows w, w+8, w+16, w+24
#pragma unroll
    for (int rr = 0; rr < 4; rr++) {
        int p = w + rr * 8;
        const float* src = pf + ((size_t)b * NP + p) * NC;
        float vals[16];
        float s = 0.f;
#pragma unroll
        for (int t = 0; t < 16; t++) {
            float v = src[lane + 32 * t];
            vals[t] = v;
            s += v * v;
        }
        s = warp_sum(s);
        float inv = 1.0f / fmaxf(sqrtf(s), 1e-12f);
#pragma unroll
        for (int t = 0; t < 16; t++) pf_s[p * PFW + lane + 32 * t] = vals[t] * inv;
    }
    __syncthreads();

    // text-text: thread (ty,tx) computes rows {ty, ty+16} x cols {tx, tx+16}
    int ty = tid >> 4, tx = tid & 15;
    const float4* r0 = (const float4*)(pf_s + ty * PFW);
    const float4* r1 = (const float4*)(pf_s + (ty + 16) * PFW);
    const float4* c0 = (const float4*)(pf_s + tx * PFW);
    const float4* c1 = (const float4*)(pf_s + (tx + 16) * PFW);
    float a00 = 0, a01 = 0, a10 = 0, a11 = 0;
#pragma unroll 4
    for (int k = 0; k < NC / 4; k++) {
        float4 A0 = r0[k], A1 = r1[k], B0 = c0[k], B1 = c1[k];
        a00 += A0.x * B0.x + A0.y * B0.y + A0.z * B0.z + A0.w * B0.w;
        a01 += A0.x * B1.x + A0.y * B1.y + A0.z * B1.z + A0.w * B1.w;
        a10 += A1.x * B0.x + A1.y * B0.y + A1.z * B0.z + A1.w * B0.w;
        a11 += A1.x * B1.x + A1.y * B1.y + A1.z * B1.z + A1.w * B1.w;
    }
    float p0s = ps_s[ty], p1s = ps_s[ty + 16];
    float q0s = ps_s[tx], q1s = ps_s[tx + 16];
    float lsum = fabsf(a00 - (1.f - 0.1f * fabsf(p0s - q0s)))
               + fabsf(a01 - (1.f - 0.1f * fabsf(p0s - q1s)))
               + fabsf(a10 - (1.f - 0.1f * fabsf(p1s - q0s)))
               + fabsf(a11 - (1.f - 0.1f * fabsf(p1s - q1s)));
    lsum = warp_sum(lsum);
    if (lane == 0) red[w] = lsum;
    __syncthreads();
    if (tid == 0) {
        float t0 = 0;
#pragma unroll
        for (int i = 0; i < 8; i++) t0 += red[i];
        atomicAdd(&g_acc[1], (double)t0);
    }

    // image-text: warp w handles pivots w, w+8, w+16, w+24
    float t_b = targets[b];
    float isum = 0.f;
#pragma unroll
    for (int rr = 0; rr < 4; rr++) {
        int p = w + rr * 8;
        float s = 0.f;
#pragma unroll
        for (int t = 0; t < 16; t++)
            s += fn_s[lane + 32 * t] * pf_s[p * PFW + lane + 32 * t];
        s = warp_sum(s);
        if (lane == 0) isum += fabsf(s - (1.f - 0.1f * fabsf(t_b - ps_s[p])));
    }
    __syncthreads();   // protect red reuse
    if (lane == 0) red[w] = isum;
    __syncthreads();
    if (tid == 0) {
        float t0 = 0;
#pragma unroll
        for (int i = 0; i < 8; i++) t0 += red[i];
        atomicAdd(&g_acc[2], (double)t0);
    }
}

// image-image: 64x64 output tile per block, upper-triangle tiles only
// (off-diagonal weighted 2x by symmetry). fp32 smem-tiled GEMM with 4x4
// register blocking, fused |dot - label| reduction.
__global__ void k_ii(const float* __restrict__ targets) {
    __shared__ __align__(16) float Asm[16][TW];
    __shared__ __align__(16) float Bsm[16][TW];
    __shared__ float tr[64], tc[64], red[8];

    // map linear block id -> (bi, bj) with bi <= bj
    int idx = blockIdx.x, bi = 0;
    while (true) {
        int len = NT - bi;
        if (idx < len) break;
        idx -= len; bi++;
    }
    int bj = bi + idx;

    int tid = threadIdx.x;  // 256
    if (tid < 64)       tr[tid]      = targets[bi * 64 + tid];
    else if (tid < 128) tc[tid - 64] = targets[bj * 64 + (tid - 64)];

    int ty = tid >> 4, tx = tid & 15;
    int lr = tid >> 2, lk = (tid & 3) * 4;
    const float* Ag = g_fn + (size_t)(bi * 64 + lr) * NC;
    const float* Bg = g_fn + (size_t)(bj * 64 + lr) * NC;

    float acc[4][4] = {};
    for (int k0 = 0; k0 < NC; k0 += 16) {
        float4 av = *(const float4*)(Ag + k0 + lk);
        float4 bv = *(const float4*)(Bg + k0 + lk);
        __syncthreads();
        Asm[lk + 0][lr] = av.x; Asm[lk + 1][lr] = av.y;
        Asm[lk + 2][lr] = av.z; Asm[lk + 3][lr] = av.w;
        Bsm[lk + 0][lr] = bv.x; Bsm[lk + 1][lr] = bv.y;
        Bsm[lk + 2][lr] = bv.z; Bsm[lk + 3][lr] = bv.w;
        __syncthreads();
#pragma unroll
        for (int k = 0; k < 16; k++) {
            float4 a = *(const float4*)&Asm[k][ty * 4];
            float4 b = *(const float4*)&Bsm[k][tx * 4];
            acc[0][0] += a.x * b.x; acc[0][1] += a.x * b.y; acc[0][2] += a.x * b.z; acc[0][3] += a.x * b.w;
            acc[1][0] += a.y * b.x; acc[1][1] += a.y * b.y; acc[1][2] += a.y * b.z; acc[1][3] += a.y * b.w;
            acc[2][0] += a.z * b.x; acc[2][1] += a.z * b.y; acc[2][2] += a.z * b.z; acc[2][3] += a.z * b.w;
            acc[3][0] += a.w * b.x; acc[3][1] += a.w * b.y; acc[3][2] += a.w * b.z; acc[3][3] += a.w * b.w;
        }
    }

    float wgt = (bi == bj) ? 1.f : 2.f;
    float lsum = 0.f;
#pragma unroll
    for (int i = 0; i < 4; i++) {
        float tri = tr[ty * 4 + i];
#pragma unroll
        for (int j = 0; j < 4; j++)
            lsum += fabsf(acc[i][j] - (1.f - 0.1f * fabsf(tri - tc[tx * 4 + j])));
    }
    lsum = warp_sum(lsum);
    int lane = tid & 31, w = tid >> 5;
    if (lane == 0) red[w] = lsum;
    __syncthreads();
    if (tid == 0) {
        float t0 = 0;
#pragma unroll
        for (int i = 0; i < 8; i++) t0 += red[i];
        atomicAdd(&g_acc[0], (double)(t0 * wgt));
    }
}

__global__ void k_final(const float* __restrict__ pred,
                        const float* __restrict__ targets,
                        float* __restrict__ out) {
    __shared__ float red[8];
    int tid = threadIdx.x;  // 256
    float s = 0.f;
    for (int i = tid; i < NB; i += 256) s += fabsf(pred[i] - targets[i]);
    s = warp_sum(s);
    if ((tid & 31) == 0) red[tid >> 5] = s;
    __syncthreads();
    if (tid == 0) {
        float mae = 0;
#pragma unroll
        for (int i = 0; i < 8; i++) mae += red[i];
        out[0] = (float)(g_acc[0] / ((double)NB * (double)NB));
        out[1] = (float)(g_acc[1] / ((double)NB * (double)NP * (double)NP));
        out[2] = (float)(g_acc[2] / ((double)NB * (double)NP));
        out[3] = mae / (float)NB;
    }
}

extern "C" void kernel_launch(void* const* d_in, const int* in_sizes, int n_in,
                              void* d_out, int out_size) {
    const float* pred    = (const float*)d_in[0];
    const float* targets = (const float*)d_in[1];
    const float* feats   = (const float*)d_in[2];
    const float* pivf    = (const float*)d_in[3];
    const float* pivs    = (const float*)d_in[4];
    float* out = (float*)d_out;

    size_t smB = (size_t)(NP * PFW + NC + NP + 16) * sizeof(float);
    cudaFuncSetAttribute(k_pivot, cudaFuncAttributeMaxDynamicSharedMemorySize, (int)smB);

    k_init<<<1, 32>>>();
    k_norm_feats<<<NB, 128>>>(feats);
    k_pivot<<<NB, 256, smB>>>(pivf, pivs, targets);
    k_ii<<<NBLK_II, 256>>>(targets);
    k_final<<<1, 256>>>(pred, targets, out);
}

// round 4
// speedup vs baseline: 2.8956x; 2.8956x over previous
#include <cuda_runtime.h>
#include <cuda_bf16.h>
#include <stdint.h>
#include <math.h>

#define NB 4096
#define NP 32
#define NC 512
#define NT 64                          // 4096/64 tile grid for ii
#define NBLK_II (NT * (NT + 1) / 2)    // 2080 upper-triangle tiles
#define SAW 72                         // padded smem row (bf16) for ii tiles
#define SPW 520                        // padded smem row (bf16) for pivot matrix

__device__ double g_acc[3];                 // [0]=ii, [1]=tt, [2]=it
__device__ __nv_bfloat16 g_fnh[NB * NC];    // L2-normalized feats, bf16

__device__ __forceinline__ float warp_sum(float v) {
#pragma unroll
    for (int o = 16; o > 0; o >>= 1) v += __shfl_xor_sync(0xffffffffu, v, o);
    return v;
}

__device__ __forceinline__ void ldsm4(uint32_t* r, uint32_t addr) {
    asm volatile("ldmatrix.sync.aligned.m8n8.x4.shared.b16 {%0,%1,%2,%3}, [%4];"
                 : "=r"(r[0]), "=r"(r[1]), "=r"(r[2]), "=r"(r[3]) : "r"(addr));
}

__device__ __forceinline__ void mma_bf16(float* d, const uint32_t* a,
                                         uint32_t b0, uint32_t b1) {
    asm volatile(
        "mma.sync.aligned.m16n8k16.row.col.f32.bf16.bf16.f32 "
        "{%0,%1,%2,%3}, {%4,%5,%6,%7}, {%8,%9}, {%0,%1,%2,%3};"
        : "+f"(d[0]), "+f"(d[1]), "+f"(d[2]), "+f"(d[3])
        : "r"(a[0]), "r"(a[1]), "r"(a[2]), "r"(a[3]), "r"(b0), "r"(b1));
}

__global__ void k_init() {
    if (threadIdx.x < 3) g_acc[threadIdx.x] = 0.0;
}

// One block per feats row: L2-normalize, write bf16 row.
__global__ void k_norm_feats(const float* __restrict__ feats) {
    __shared__ float red[4];
    int b = blockIdx.x, t = threadIdx.x;  // 128 threads, 128 float4/row
    const float4* src = (const float4*)(feats + (size_t)b * NC);
    float4 v = src[t];
    float s = v.x * v.x + v.y * v.y + v.z * v.z + v.w * v.w;
    s = warp_sum(s);
    if ((t & 31) == 0) red[t >> 5] = s;
    __syncthreads();
    float tot = red[0] + red[1] + red[2] + red[3];
    float inv = 1.0f / fmaxf(sqrtf(tot), 1e-12f);
    __nv_bfloat162* dst = (__nv_bfloat162*)(g_fnh + (size_t)b * NC);
    dst[2 * t]     = __floats2bfloat162_rn(v.x * inv, v.y * inv);
    dst[2 * t + 1] = __floats2bfloat162_rn(v.z * inv, v.w * inv);
}

// One block per batch b: normalize pivots into bf16 smem (rows 0-31),
// append normalized feats row (row 32), zero-pad to 48 rows, then 48x32
// gram via mma with k-split over 8 warps. Fused tt + it loss epilogue.
__global__ void __launch_bounds__(256) k_pivot(const float* __restrict__ pf,
                                               const float* __restrict__ ps,
                                               const float* __restrict__ targets) {
    extern __shared__ char smraw[];
    __nv_bfloat16* pfh = (__nv_bfloat16*)smraw;      // 48 * SPW
    float* part = (float*)(smraw + 48 * SPW * 2);    // 8 * 1536
    float* ps_s = part + 8 * 1536;                   // 32
    float* red  = ps_s + 32;                         // 16

    int b = blockIdx.x, tid = threadIdx.x, lane = tid & 31, w = tid >> 5;

    if (tid < 32) ps_s[tid] = ps[b * NP + tid];

    // normalize pivot rows: warp w handles rows w, w+8, w+16, w+24
#pragma unroll
    for (int rr = 0; rr < 4; rr++) {
        int p = w + rr * 8;
        const float* src = pf + ((size_t)b * NP + p) * NC;
        float vals[16];
        float s = 0.f;
#pragma unroll
        for (int t = 0; t < 16; t++) {
            float v = src[lane + 32 * t];
            vals[t] = v;
            s += v * v;
        }
        s = warp_sum(s);
        float inv = 1.0f / fmaxf(sqrtf(s), 1e-12f);
#pragma unroll
        for (int t = 0; t < 16; t++)
            pfh[p * SPW + lane + 32 * t] = __float2bfloat16_rn(vals[t] * inv);
    }
    // row 32 = normalized feats row b (already bf16)
    {
        const uint4* src = (const uint4*)(g_fnh + (size_t)b * NC);
        for (int i = tid; i < 64; i += 256)
            *(uint4*)(pfh + 32 * SPW + i * 8) = src[i];
    }
    // zero rows 33..47
    for (int i = tid; i < 15 * 64; i += 256) {
        int r = 33 + i / 64, c = (i % 64) * 8;
        *(uint4*)(pfh + r * SPW + c) = make_uint4(0, 0, 0, 0);
    }
    __syncthreads();

    // mma phase: warp w owns k-slice [64w, 64w+64)
    uint32_t base = (uint32_t)__cvta_generic_to_shared(pfh);
    int kslice = w * 64;
    int w8 = lane & 7;
    uint32_t aAddr[3], bAddr[2];
#pragma unroll
    for (int m = 0; m < 3; m++) {
        int row  = 16 * m + ((lane >> 3) & 1) * 8 + w8;
        int koff = (lane >> 4) * 8;
        aAddr[m] = base + (uint32_t)(row * SPW + kslice + koff) * 2;
    }
#pragma unroll
    for (int p = 0; p < 2; p++) {
        int col  = 16 * p + ((lane >> 4) & 1) * 8 + w8;
        int koff = ((lane >> 3) & 1) * 8;
        bAddr[p] = base + (uint32_t)(col * SPW + kslice + koff) * 2;
    }

    float acc[3][4][4] = {};
#pragma unroll
    for (int ks = 0; ks < 4; ks++) {
        uint32_t a[3][4], bb[2][4];
#pragma unroll
        for (int m = 0; m < 3; m++) ldsm4(a[m], aAddr[m] + ks * 32);
#pragma unroll
        for (int p = 0; p < 2; p++) ldsm4(bb[p], bAddr[p] + ks * 32);
#pragma unroll
        for (int m = 0; m < 3; m++) {
#pragma unroll
            for (int n = 0; n < 4; n++) {
                mma_bf16(acc[m][n], a[m], bb[n >> 1][(n & 1) * 2],
                         bb[n >> 1][(n & 1) * 2 + 1]);
            }
        }
    }

    // store per-warp partial 48x32 gram
    float* my = part + w * 1536;
#pragma unroll
    for (int m = 0; m < 3; m++) {
#pragma unroll
        for (int n = 0; n < 4; n++) {
            int r0 = 16 * m + (lane >> 2);
            int c0 = 8 * n + 2 * (lane & 3);
            my[r0 * 32 + c0]           = acc[m][n][0];
            my[r0 * 32 + c0 + 1]       = acc[m][n][1];
            my[(r0 + 8) * 32 + c0]     = acc[m][n][2];
            my[(r0 + 8) * 32 + c0 + 1] = acc[m][n][3];
        }
    }
    __syncthreads();

    // reduce across warps + loss epilogue
    float tb = targets[b];
    float tt = 0.f, it = 0.f;
#pragma unroll
    for (int e0 = 0; e0 < 6; e0++) {
        int e = tid + 256 * e0;  // 0..1535
        float s = 0.f;
#pragma unroll
        for (int ww = 0; ww < 8; ww++) s += part[ww * 1536 + e];
        int p = e >> 5, q = e & 31;
        if (p < 32) {
            tt += fabsf(s - (1.f - 0.1f * fabsf(ps_s[p] - ps_s[q])));
        } else if (p == 32) {
            it += fabsf(s - (1.f - 0.1f * fabsf(tb - ps_s[q])));
        }
    }
    tt = warp_sum(tt);
    it = warp_sum(it);
    if (lane == 0) { red[w] = tt; red[8 + w] = it; }
    __syncthreads();
    if (tid == 0) {
        float t0 = 0.f, t1 = 0.f;
#pragma unroll
        for (int i = 0; i < 8; i++) { t0 += red[i]; t1 += red[8 + i]; }
        atomicAdd(&g_acc[1], (double)t0);
        atomicAdd(&g_acc[2], (double)t1);
    }
}

// image-image: 64x64 tile per block (upper triangle, off-diag weighted 2x),
// bf16 tensor-core GEMM (mma.sync m16n8k16) with fused |dot - label| reduce.
__global__ void __launch_bounds__(128) k_ii(const float* __restrict__ targets) {
    __shared__ __align__(16) __nv_bfloat16 As[64 * SAW];
    __shared__ __align__(16) __nv_bfloat16 Bs[64 * SAW];
    __shared__ float tr[64], tc[64], red[4];

    // linear block id -> (bi, bj), bi <= bj
    int idx = blockIdx.x, bi = 0;
    while (true) {
        int len = NT - bi;
        if (idx < len) break;
        idx -= len; bi++;
    }
    int bj = bi + idx;

    int tid = threadIdx.x, lane = tid & 31, w = tid >> 5;
    if (tid < 64) tr[tid]      = targets[bi * 64 + tid];
    else          tc[tid - 64] = targets[bj * 64 + (tid - 64)];

    int wy = w >> 1, wx = w & 1;  // warp tile 32x32 within 64x64
    uint32_t asBase = (uint32_t)__cvta_generic_to_shared(As);
    uint32_t bsBase = (uint32_t)__cvta_generic_to_shared(Bs);
    int w8 = lane & 7;
    uint32_t aAddr[2], bAddr[2];
#pragma unroll
    for (int m = 0; m < 2; m++) {
        int row  = 32 * wy + 16 * m + ((lane >> 3) & 1) * 8 + w8;
        int koff = (lane >> 4) * 8;
        aAddr[m] = asBase + (uint32_t)(row * SAW + koff) * 2;
    }
#pragma unroll
    for (int p = 0; p < 2; p++) {
        int col  = 32 * wx + 16 * p + ((lane >> 4) & 1) * 8 + w8;
        int koff = ((lane >> 3) & 1) * 8;
        bAddr[p] = bsBase + (uint32_t)(col * SAW + koff) * 2;
    }

    const __nv_bfloat16* Ag = g_fnh + (size_t)(bi * 64) * NC;
    const __nv_bfloat16* Bg = g_fnh + (size_t)(bj * 64) * NC;

    float acc[2][4][4] = {};
    for (int k0 = 0; k0 < NC; k0 += 64) {
        __syncthreads();
#pragma unroll
        for (int r = 0; r < 4; r++) {
            int id = tid + 128 * r;          // 0..511
            int row = id >> 3, ch = id & 7;  // 64 rows x 8 16B-chunks
            uint4 va = *(const uint4*)(Ag + (size_t)row * NC + k0 + ch * 8);
            uint4 vb = *(const uint4*)(Bg + (size_t)row * NC + k0 + ch * 8);
            *(uint4*)(As + row * SAW + ch * 8) = va;
            *(uint4*)(Bs + row * SAW + ch * 8) = vb;
        }
        __syncthreads();
#pragma unroll
        for (int ks = 0; ks < 4; ks++) {
            uint32_t a[2][4], bb[2][4];
#pragma unroll
            for (int m = 0; m < 2; m++) ldsm4(a[m], aAddr[m] + ks * 32);
#pragma unroll
            for (int p = 0; p < 2; p++) ldsm4(bb[p], bAddr[p] + ks * 32);
#pragma unroll
            for (int m = 0; m < 2; m++) {
#pragma unroll
                for (int n = 0; n < 4; n++) {
                    mma_bf16(acc[m][n], a[m], bb[n >> 1][(n & 1) * 2],
                             bb[n >> 1][(n & 1) * 2 + 1]);
                }
            }
        }
    }

    float lsum = 0.f;
#pragma unroll
    for (int m = 0; m < 2; m++) {
#pragma unroll
        for (int n = 0; n < 4; n++) {
            int r0 = 32 * wy + 16 * m + (lane >> 2);
            int c0 = 32 * wx + 8 * n + 2 * (lane & 3);
            float tr0 = tr[r0], tr8 = tr[r0 + 8];
            float tc0 = tc[c0], tc1 = tc[c0 + 1];
            lsum += fabsf(acc[m][n][0] - (1.f - 0.1f * fabsf(tr0 - tc0)));
            lsum += fabsf(acc[m][n][1] - (1.f - 0.1f * fabsf(tr0 - tc1)));
            lsum += fabsf(acc[m][n][2] - (1.f - 0.1f * fabsf(tr8 - tc0)));
            lsum += fabsf(acc[m][n][3] - (1.f - 0.1f * fabsf(tr8 - tc1)));
        }
    }
    lsum = warp_sum(lsum);
    if (lane == 0) red[w] = lsum;
    __syncthreads();
    if (tid == 0) {
        float wgt = (bi == bj) ? 1.f : 2.f;
        float t0 = red[0] + red[1] + red[2] + red[3];
        atomicAdd(&g_acc[0], (double)(t0 * wgt));
    }
}

__global__ void k_final(const float* __restrict__ pred,
                        const float* __restrict__ targets,
                        float* __restrict__ out) {
    __shared__ float red[8];
    int tid = threadIdx.x;  // 256
    float s = 0.f;
    for (int i = tid; i < NB; i += 256) s += fabsf(pred[i] - targets[i]);
    s = warp_sum(s);
    if ((tid & 31) == 0) red[tid >> 5] = s;
    __syncthreads();
    if (tid == 0) {
        float mae = 0.f;
#pragma unroll
        for (int i = 0; i < 8; i++) mae += red[i];
        out[0] = (float)(g_acc[0] / ((double)NB * (double)NB));
        out[1] = (float)(g_acc[1] / ((double)NB * (double)NP * (double)NP));
        out[2] = (float)(g_acc[2] / ((double)NB * (double)NP));
        out[3] = mae / (float)NB;
    }
}

extern "C" void kernel_launch(void* const* d_in, const int* in_sizes, int n_in,
                              void* d_out, int out_size) {
    const float* pred    = (const float*)d_in[0];
    const float* targets = (const float*)d_in[1];
    const float* feats   = (const float*)d_in[2];
    const float* pivf    = (const float*)d_in[3];
    const float* pivs    = (const float*)d_in[4];
    float* out = (float*)d_out;

    size_t smB = (size_t)(48 * SPW * 2) + (size_t)(8 * 1536 + 32 + 16) * sizeof(float);
    cudaFuncSetAttribute(k_pivot, cudaFuncAttributeMaxDynamicSharedMemorySize, (int)smB);

    k_init<<<1, 32>>>();
    k_norm_feats<<<NB, 128>>>(feats);
    k_pivot<<<NB, 256, smB>>>(pivf, pivs, targets);
    k_ii<<<NBLK_II, 128>>>(targets);
    k_final<<<1, 256>>>(pred, targets, out);
}

// round 6
// speedup vs baseline: 3.4831x; 1.2029x over previous
#include <cuda_runtime.h>
#include <cuda_bf16.h>
#include <stdint.h>
#include <math.h>

#define NB 4096
#define NP 32
#define NC 512
#define NT2 32                          // 4096/128 tile grid for ii
#define NBLK_II (NT2 * (NT2 + 1) / 2)   // 528 upper-triangle tiles
#define SAW 72                          // padded smem row (bf16) for ii tiles
#define BUFSZ (128 * SAW * 2)           // bytes per 128x64 bf16 buffer
#define SPW 520                         // padded smem row (bf16) for pivot matrix

__device__ double g_acc[3];                 // [0]=ii, [1]=tt, [2]=it
__device__ __nv_bfloat16 g_fnh[NB * NC];    // L2-normalized feats, bf16

__device__ __forceinline__ float warp_sum(float v) {
#pragma unroll
    for (int o = 16; o > 0; o >>= 1) v += __shfl_xor_sync(0xffffffffu, v, o);
    return v;
}

__device__ __forceinline__ void ldsm4(uint32_t* r, uint32_t addr) {
    asm volatile("ldmatrix.sync.aligned.m8n8.x4.shared.b16 {%0,%1,%2,%3}, [%4];"
                 : "=r"(r[0]), "=r"(r[1]), "=r"(r[2]), "=r"(r[3]) : "r"(addr));
}

__device__ __forceinline__ void mma_bf16(float* d, const uint32_t* a,
                                         uint32_t b0, uint32_t b1) {
    asm volatile(
        "mma.sync.aligned.m16n8k16.row.col.f32.bf16.bf16.f32 "
        "{%0,%1,%2,%3}, {%4,%5,%6,%7}, {%8,%9}, {%0,%1,%2,%3};"
        : "+f"(d[0]), "+f"(d[1]), "+f"(d[2]), "+f"(d[3])
        : "r"(a[0]), "r"(a[1]), "r"(a[2]), "r"(a[3]), "r"(b0), "r"(b1));
}

__device__ __forceinline__ void cp16(uint32_t saddr, const void* gptr) {
    asm volatile("cp.async.cg.shared.global [%0], [%1], 16;"
                 :: "r"(saddr), "l"(gptr) : "memory");
}
#define CP_COMMIT() asm volatile("cp.async.commit_group;" ::: "memory")
#define CP_WAIT(N)  asm volatile("cp.async.wait_group %0;" :: "n"(N) : "memory")

__global__ void k_init() {
    if (threadIdx.x < 3) g_acc[threadIdx.x] = 0.0;
}

// One block per feats row: L2-normalize, write bf16 row.
__global__ void k_norm_feats(const float* __restrict__ feats) {
    __shared__ float red[4];
    int b = blockIdx.x, t = threadIdx.x;  // 128 threads, 128 float4/row
    const float4* src = (const float4*)(feats + (size_t)b * NC);
    float4 v = src[t];
    float s = v.x * v.x + v.y * v.y + v.z * v.z + v.w * v.w;
    s = warp_sum(s);
    if ((t & 31) == 0) red[t >> 5] = s;
    __syncthreads();
    float tot = red[0] + red[1] + red[2] + red[3];
    float inv = 1.0f / fmaxf(sqrtf(tot), 1e-12f);
    __nv_bfloat162* dst = (__nv_bfloat162*)(g_fnh + (size_t)b * NC);
    dst[2 * t]     = __floats2bfloat162_rn(v.x * inv, v.y * inv);
    dst[2 * t + 1] = __floats2bfloat162_rn(v.z * inv, v.w * inv);
}

// One block per batch b: normalize pivots into bf16 smem (rows 0-31),
// append normalized feats row (row 32), zero-pad to 48 rows, 48x32 gram
// via mma with k-split over 8 warps. Fused tt + it loss epilogue.
__global__ void __launch_bounds__(256) k_pivot(const float* __restrict__ pf,
                                               const float* __restrict__ ps,
                                               const float* __restrict__ targets) {
    extern __shared__ char smraw[];
    __nv_bfloat16* pfh = (__nv_bfloat16*)smraw;      // 48 * SPW
    float* part = (float*)(smraw + 48 * SPW * 2);    // 8 * 1536
    float* ps_s = part + 8 * 1536;                   // 32
    float* red  = ps_s + 32;                         // 16

    int b = blockIdx.x, tid = threadIdx.x, lane = tid & 31, w = tid >> 5;

    if (tid < 32) ps_s[tid] = ps[b * NP + tid];

    // normalize pivot rows: warp w handles rows w, w+8, w+16, w+24.
    // Vectorized LDG.128, all 16 loads issued before reductions (MLP=16).
    {
        float4 vals[4][4];
#pragma unroll
        for (int rr = 0; rr < 4; rr++) {
            int p = w + rr * 8;
            const float4* src4 = (const float4*)(pf + ((size_t)b * NP + p) * NC);
#pragma unroll
            for (int t = 0; t < 4; t++) vals[rr][t] = src4[lane + 32 * t];
        }
        float sums[4];
#pragma unroll
        for (int rr = 0; rr < 4; rr++) {
            float s = 0.f;
#pragma unroll
            for (int t = 0; t < 4; t++) {
                float4 v = vals[rr][t];
                s += v.x * v.x + v.y * v.y + v.z * v.z + v.w * v.w;
            }
            sums[rr] = warp_sum(s);
        }
#pragma unroll
        for (int rr = 0; rr < 4; rr++) {
            int p = w + rr * 8;
            float inv = 1.0f / fmaxf(sqrtf(sums[rr]), 1e-12f);
            __nv_bfloat162* dst = (__nv_bfloat162*)(pfh + p * SPW);
#pragma unroll
            for (int t = 0; t < 4; t++) {
                float4 v = vals[rr][t];
                int i = lane + 32 * t;
                dst[2 * i]     = __floats2bfloat162_rn(v.x * inv, v.y * inv);
                dst[2 * i + 1] = __floats2bfloat162_rn(v.z * inv, v.w * inv);
            }
        }
    }
    // row 32 = normalized feats row b (already bf16)
    {
        const uint4* src = (const uint4*)(g_fnh + (size_t)b * NC);
        for (int i = tid; i < 64; i += 256)
            *(uint4*)(pfh + 32 * SPW + i * 8) = src[i];
    }
    // zero rows 33..47
    for (int i = tid; i < 15 * 64; i += 256) {
        int r = 33 + i / 64, c = (i % 64) * 8;
        *(uint4*)(pfh + r * SPW + c) = make_uint4(0, 0, 0, 0);
    }
    __syncthreads();

    // mma phase: warp w owns k-slice [64w, 64w+64)
    uint32_t base = (uint32_t)__cvta_generic_to_shared(pfh);
    int kslice = w * 64;
    int w8 = lane & 7;
    uint32_t aAddr[3], bAddr[2];
#pragma unroll
    for (int m = 0; m < 3; m++) {
        int row  = 16 * m + ((lane >> 3) & 1) * 8 + w8;
        int koff = (lane >> 4) * 8;
        aAddr[m] = base + (uint32_t)(row * SPW + kslice + koff) * 2;
    }
#pragma unroll
    for (int p = 0; p < 2; p++) {
        int col  = 16 * p + ((lane >> 4) & 1) * 8 + w8;
        int koff = ((lane >> 3) & 1) * 8;
        bAddr[p] = base + (uint32_t)(col * SPW + kslice + koff) * 2;
    }

    float acc[3][4][4] = {};
#pragma unroll
    for (int ks = 0; ks < 4; ks++) {
        uint32_t a[3][4], bb[2][4];
#pragma unroll
        for (int m = 0; m < 3; m++) ldsm4(a[m], aAddr[m] + ks * 32);
#pragma unroll
        for (int p = 0; p < 2; p++) ldsm4(bb[p], bAddr[p] + ks * 32);
#pragma unroll
        for (int m = 0; m < 3; m++) {
#pragma unroll
            for (int n = 0; n < 4; n++) {
                mma_bf16(acc[m][n], a[m], bb[n >> 1][(n & 1) * 2],
                         bb[n >> 1][(n & 1) * 2 + 1]);
            }
        }
    }

    // store per-warp partial 48x32 gram
    float* my = part + w * 1536;
#pragma unroll
    for (int m = 0; m < 3; m++) {
#pragma unroll
        for (int n = 0; n < 4; n++) {
            int r0 = 16 * m + (lane >> 2);
            int c0 = 8 * n + 2 * (lane & 3);
            my[r0 * 32 + c0]           = acc[m][n][0];
            my[r0 * 32 + c0 + 1]       = acc[m][n][1];
            my[(r0 + 8) * 32 + c0]     = acc[m][n][2];
            my[(r0 + 8) * 32 + c0 + 1] = acc[m][n][3];
        }
    }
    __syncthreads();

    // reduce across warps + loss epilogue
    float tb = targets[b];
    float tt = 0.f, it = 0.f;
#pragma unroll
    for (int e0 = 0; e0 < 6; e0++) {
        int e = tid + 256 * e0;  // 0..1535
        float s = 0.f;
#pragma unroll
        for (int ww = 0; ww < 8; ww++) s += part[ww * 1536 + e];
        int p = e >> 5, q = e & 31;
        if (p < 32) {
            tt += fabsf(s - (1.f - 0.1f * fabsf(ps_s[p] - ps_s[q])));
        } else if (p == 32) {
            it += fabsf(s - (1.f - 0.1f * fabsf(tb - ps_s[q])));
        }
    }
    tt = warp_sum(tt);
    it = warp_sum(it);
    if (lane == 0) { red[w] = tt; red[8 + w] = it; }
    __syncthreads();
    if (tid == 0) {
        float t0 = 0.f, t1 = 0.f;
#pragma unroll
        for (int i = 0; i < 8; i++) { t0 += red[i]; t1 += red[8 + i]; }
        atomicAdd(&g_acc[1], (double)t0);
        atomicAdd(&g_acc[2], (double)t1);
    }
}

// image-image v2: 128x128 tile per block (upper triangle, off-diag 2x),
// cp.async double-buffered bf16 mma pipeline, fused |dot - label| reduce.
// 8 warps, warp tile 32x64, BK=64, 8 k-stages.
__global__ void __launch_bounds__(256, 1) k_ii(const float* __restrict__ targets) {
    extern __shared__ __align__(16) __nv_bfloat16 sm[];  // As0|As1|Bs0|Bs1
    __shared__ float tr[128], tc[128], red[8];

    // linear block id -> (bi, bj), bi <= bj
    int idx = blockIdx.x, bi = 0;
    while (true) {
        int len = NT2 - bi;
        if (idx < len) break;
        idx -= len; bi++;
    }
    int bj = bi + idx;

    int tid = threadIdx.x, lane = tid & 31, w = tid >> 5;
    if (tid < 128) tr[tid]       = targets[bi * 128 + tid];
    else           tc[tid - 128] = targets[bj * 128 + (tid - 128)];

    uint32_t smBase = (uint32_t)__cvta_generic_to_shared(sm);
    const __nv_bfloat16* Ag = g_fnh + (size_t)(bi * 128) * NC;
    const __nv_bfloat16* Bg = g_fnh + (size_t)(bj * 128) * NC;

    // cp.async chunk map: 1024 16B-chunks per tile, 4 per thread
    int crow[4], cch[4];
#pragma unroll
    for (int i = 0; i < 4; i++) {
        int c = tid + 256 * i;
        crow[i] = c >> 3;
        cch[i]  = (c & 7) * 8;   // bf16 offset within row
    }

    // ldmatrix offsets relative to buffer base (bytes)
    int wy = w >> 1, wx = w & 1;   // warp grid 4x2, warp tile 32x64
    int w8 = lane & 7;
    uint32_t aOff[2], bOff[4];
#pragma unroll
    for (int m = 0; m < 2; m++) {
        int row  = 32 * wy + 16 * m + ((lane >> 3) & 1) * 8 + w8;
        int koff = (lane >> 4) * 8;
        aOff[m] = (uint32_t)(row * SAW + koff) * 2;
    }
#pragma unroll
    for (int p = 0; p < 4; p++) {
        int col  = 64 * wx + 16 * p + ((lane >> 4) & 1) * 8 + w8;
        int koff = ((lane >> 3) & 1) * 8;
        bOff[p] = (uint32_t)(col * SAW + koff) * 2;
    }

    // prologue: stages 0 and 1 into buffers 0 and 1
#pragma unroll
    for (int s = 0; s < 2; s++) {
        uint32_t abase = smBase + s * BUFSZ;
        uint32_t bbase = smBase + 2 * BUFSZ + s * BUFSZ;
        int k0 = s * 64;
#pragma unroll
        for (int i = 0; i < 4; i++) {
            cp16(abase + (uint32_t)(crow[i] * SAW + cch[i]) * 2,
                 Ag + (size_t)crow[i] * NC + k0 + cch[i]);
            cp16(bbase + (uint32_t)(crow[i] * SAW + cch[i]) * 2,
                 Bg + (size_t)crow[i] * NC + k0 + cch[i]);
        }
        CP_COMMIT();
    }

    float acc[2][8][4] = {};
#pragma unroll
    for (int k0 = 0; k0 < 8; k0++) {
        if (k0 == 7) { CP_WAIT(0); } else { CP_WAIT(1); }
        __syncthreads();
        int buf = k0 & 1;
        uint32_t abase = smBase + buf * BUFSZ;
        uint32_t bbase = smBase + 2 * BUFSZ + buf * BUFSZ;
#pragma unroll
        for (int ks = 0; ks < 4; ks++) {
            uint32_t a[2][4], bb[4][4];
#pragma unroll
            for (int m = 0; m < 2; m++) ldsm4(a[m], abase + aOff[m] + ks * 32);
#pragma unroll
            for (int p = 0; p < 4; p++) ldsm4(bb[p], bbase + bOff[p] + ks * 32);
#pragma unroll
            for (int m = 0; m < 2; m++) {
#pragma unroll
                for (int n = 0; n < 8; n++) {
                    mma_bf16(acc[m][n], a[m], bb[n >> 1][(n & 1) * 2],
                             bb[n >> 1][(n & 1) * 2 + 1]);
                }
            }
        }
        __syncthreads();
        if (k0 + 2 < 8) {
            int s = k0 + 2, kk = s * 64, nbuf = s & 1;
            uint32_t na = smBase + nbuf * BUFSZ;
            uint32_t nb = smBase + 2 * BUFSZ + nbuf * BUFSZ;
#pragma unroll
            for (int i = 0; i < 4; i++) {
                cp16(na + (uint32_t)(crow[i] * SAW + cch[i]) * 2,
                     Ag + (size_t)crow[i] * NC + kk + cch[i]);
                cp16(nb + (uint32_t)(crow[i] * SAW + cch[i]) * 2,
                     Bg + (size_t)crow[i] * NC + kk + cch[i]);
            }
            CP_COMMIT();
        }
    }

    float lsum = 0.f;
#pragma unroll
    for (int m = 0; m < 2; m++) {
#pragma unroll
        for (int n = 0; n < 8; n++) {
            int r0 = 32 * wy + 16 * m + (lane >> 2);
            int c0 = 64 * wx + 8 * n + 2 * (lane & 3);
            float tr0 = tr[r0], tr8 = tr[r0 + 8];
            float tc0 = tc[c0], tc1 = tc[c0 + 1];
            lsum += fabsf(acc[m][n][0] - (1.f - 0.1f * fabsf(tr0 - tc0)));
            lsum += fabsf(acc[m][n][1] - (1.f - 0.1f * fabsf(tr0 - tc1)));
            lsum += fabsf(acc[m][n][2] - (1.f - 0.1f * fabsf(tr8 - tc0)));
            lsum += fabsf(acc[m][n][3] - (1.f - 0.1f * fabsf(tr8 - tc1)));
        }
    }
    lsum = warp_sum(lsum);
    if (lane == 0) red[w] = lsum;
    __syncthreads();
    if (tid == 0) {
        float wgt = (bi == bj) ? 1.f : 2.f;
        float t0 = 0.f;
#pragma unroll
        for (int i = 0; i < 8; i++) t0 += red[i];
        atomicAdd(&g_acc[0], (double)(t0 * wgt));
    }
}

__global__ void k_final(const float* __restrict__ pred,
                        const float* __restrict__ targets,
                        float* __restrict__ out) {
    __shared__ float red[8];
    int tid = threadIdx.x;  // 256
    float s = 0.f;
    for (int i = tid; i < NB; i += 256) s += fabsf(pred[i] - targets[i]);
    s = warp_sum(s);
    if ((tid & 31) == 0) red[tid >> 5] = s;
    __syncthreads();
    if (tid == 0) {
        float mae = 0.f;
#pragma unroll
        for (int i = 0; i < 8; i++) mae += red[i];
        out[0] = (float)(g_acc[0] / ((double)NB * (double)NB));
        out[1] = (float)(g_acc[1] / ((double)NB * (double)NP * (double)NP));
        out[2] = (float)(g_acc[2] / ((double)NB * (double)NP));
        out[3] = mae / (float)NB;
    }
}

extern "C" void kernel_launch(void* const* d_in, const int* in_sizes, int n_in,
                              void* d_out, int out_size) {
    const float* pred    = (const float*)d_in[0];
    const float* targets = (const float*)d_in[1];
    const float* feats   = (const float*)d_in[2];
    const float* pivf    = (const float*)d_in[3];
    const float* pivs    = (const float*)d_in[4];
    float* out = (float*)d_out;

    size_t smPivot = (size_t)(48 * SPW * 2) + (size_t)(8 * 1536 + 32 + 16) * sizeof(float);
    size_t smII = (size_t)(4 * BUFSZ);   // 73728 bytes
    cudaFuncSetAttribute(k_pivot, cudaFuncAttributeMaxDynamicSharedMemorySize, (int)smPivot);
    cudaFuncSetAttribute(k_ii, cudaFuncAttributeMaxDynamicSharedMemorySize, (int)smII);

    k_init<<<1, 32>>>();
    k_norm_feats<<<NB, 128>>>(feats);
    k_pivot<<<NB, 256, smPivot>>>(pivf, pivs, targets);
    k_ii<<<NBLK_II, 256, smII>>>(targets);
    k_final<<<1, 256>>>(pred, targets, out);
}